// round 9
// baseline (speedup 1.0000x reference)
#include <cuda_runtime.h>

#define BATCH 4096
#define SEQ   4096
#define BT    (BATCH * SEQ)

static __device__ __forceinline__ float ex2f_(float x) {
    float y; asm("ex2.approx.f32 %0, %1;" : "=f"(y) : "f"(x)); return y;
}
static __device__ __forceinline__ float rcpf_(float x) {
    float y; asm("rcp.approx.f32 %0, %1;" : "=f"(y) : "f"(x)); return y;
}
static __device__ __forceinline__ float tanhf_(float x) {
    float y; asm("tanh.approx.f32 %0, %1;" : "=f"(y) : "f"(x)); return y;
}

// ---------------------------------------------------------------------------
// Scan kernel: one thread = one chain; 1 warp/SM; latency-bound.
// 8-step unrolled bodies (vs 4 in the 356us baseline): halves per-iteration
// branch/select/address overhead; next chunk's 8 x-values prefetched into a
// register array a full body (~8-16 steps, >1200 cyc) ahead of use.
//
// Step (all gates MUFU.TANH):
//   r = 0.5*tanh(sr)+0.5 ; z likewise ; n = tanh(sn)
//   sn = tr*hhn + c2 ;  hhn = wn2*h + bn2 ;  c2 = wn2*h + pxn
//   h' = omz*tn + u ;   omz = 0.5 - 0.5*tz ;  u = (0.5*h)*tz + 0.5*h
// Recurrence path: FMA(4)+TANH(16)+FMA(4)+TANH(16)+FMA(4) = 44 cyc.
// ---------------------------------------------------------------------------
__global__ void __launch_bounds__(32, 1) gru_scan_kernel(
    const float* __restrict__ xi,    // (B, T, 2): [x, label]
    const float* __restrict__ Wih,   // (3,2) rows r,z,n
    const float* __restrict__ Whh,   // (3,)
    const float* __restrict__ bih,   // (3,)
    const float* __restrict__ bhh,   // (3,)
    float* __restrict__ hraw)        // (B, T) raw h
{
    const int b = blockIdx.x * 32 + threadIdx.x;

    const size_t rowoff = (size_t)b * (SEQ * 2);
    const float4* __restrict__ xrow = (const float4*)(xi + rowoff);
    const float label = xi[rowoff + 1];

    const float Ar = Wih[0], Br = Wih[1];
    const float Az = Wih[2], Bz = Wih[3];
    const float An = Wih[4], Bn = Wih[5];
    const float Wr = Whh[0], Wz = Whh[1], Wn = Whh[2];

    const float ar2 = 0.5f * Ar, wr2 = 0.5f * Wr;
    const float cr2 = 0.5f * (Br * label + bih[0] + bhh[0]);
    const float az2 = 0.5f * Az, wz2 = 0.5f * Wz;
    const float cz2 = 0.5f * (Bz * label + bih[1] + bhh[1]);
    const float wn2 = 0.5f * Wn, bn2 = 0.5f * bhh[2];
    const float anx = An;
    const float cnx = Bn * label + bih[2] + bn2;

    float h = 0.0f;
    float4* __restrict__ orow = (float4*)(hraw + (size_t)b * SEQ);

    // Current / next chunk x-values (8 timesteps each), register-resident.
    float xb[8], xn[8];

    // Prime chunk 0: 4x LDG.128; keep x (.x/.z); label (.y/.w) is constant.
    #pragma unroll
    for (int i = 0; i < 4; ++i) {
        float4 v = xrow[i];
        xb[2 * i]     = v.x;
        xb[2 * i + 1] = v.z;
    }

    const int NC8 = SEQ / 8;  // 512 chunks of 8 steps
    for (int c = 0; c < NC8; ++c) {
        const int cn = (c + 1 < NC8) ? (c + 1) : c;
        const float4* __restrict__ nrow = xrow + cn * 4;

        // Prefetch next chunk (loads issue here, consumed one body later).
        #pragma unroll
        for (int i = 0; i < 4; ++i) {
            float4 v = nrow[i];
            xn[2 * i]     = v.x;
            xn[2 * i + 1] = v.z;
        }

        float y[8];
        #pragma unroll
        for (int s = 0; s < 8; ++s) {
            const float x   = xb[s];
            const float pxr = fmaf(ar2, x, cr2);
            const float pxz = fmaf(az2, x, cz2);
            const float pxn = fmaf(anx, x, cnx);

            const float sr  = fmaf(wr2, h, pxr);
            const float sz  = fmaf(wz2, h, pxz);
            const float hhn = fmaf(wn2, h, bn2);
            const float c2  = fmaf(wn2, h, pxn);
            const float tr  = tanhf_(sr);
            const float tz  = tanhf_(sz);
            const float u   = fmaf(0.5f * h, tz, 0.5f * h);
            const float omz = fmaf(-0.5f, tz, 0.5f);
            const float sn  = fmaf(tr, hhn, c2);
            const float tn  = tanhf_(sn);
            h = fmaf(omz, tn, u);
            y[s] = h;
        }

        // 2x STG.128
        orow[c * 2]     = make_float4(y[0], y[1], y[2], y[3]);
        orow[c * 2 + 1] = make_float4(y[4], y[5], y[6], y[7]);

        #pragma unroll
        for (int i = 0; i < 8; ++i)
            xb[i] = xn[i];
    }
}

// ---------------------------------------------------------------------------
// Finish kernel: in-place accurate tanh on raw h + labels broadcast fill.
// ---------------------------------------------------------------------------
__global__ void finish_kernel(float4* __restrict__ out,        // BT/4 elems
                              const float* __restrict__ labels,
                              float4* __restrict__ outl)       // or nullptr
{
    const float S = -2.0f * 1.44269504088896340736f;
    int i = blockIdx.x * blockDim.x + threadIdx.x;
    float4 v = out[i];
    v.x = fmaf(2.0f, rcpf_(1.0f + ex2f_(S * v.x)), -1.0f);
    v.y = fmaf(2.0f, rcpf_(1.0f + ex2f_(S * v.y)), -1.0f);
    v.z = fmaf(2.0f, rcpf_(1.0f + ex2f_(S * v.z)), -1.0f);
    v.w = fmaf(2.0f, rcpf_(1.0f + ex2f_(S * v.w)), -1.0f);
    out[i] = v;
    if (outl) {
        const int bb = i >> 10;                     // SEQ/4 float4 per row
        const float lab = __ldg(labels + (size_t)bb * SEQ);
        outl[i] = make_float4(lab, lab, lab, lab);
    }
}

extern "C" void kernel_launch(void* const* d_in, const int* in_sizes, int n_in,
                              void* d_out, int out_size)
{
    const float* xi     = (const float*)d_in[0];
    const float* labels = (const float*)d_in[1];
    const float* Wih    = (const float*)d_in[2];
    const float* Whh    = (const float*)d_in[3];
    const float* bih    = (const float*)d_in[4];
    const float* bhh    = (const float*)d_in[5];

    float* out  = (float*)d_out;
    float* outl = (out_size >= 2 * BT) ? (out + (size_t)BT) : (float*)0;

    gru_scan_kernel<<<BATCH / 32, 32>>>(xi, Wih, Whh, bih, bhh, out);

    const int N4 = BT / 4;
    finish_kernel<<<N4 / 256, 256>>>((float4*)out, labels, (float4*)outl);
}

// round 10
// speedup vs baseline: 1.0507x; 1.0507x over previous
#include <cuda_runtime.h>

#define BATCH 4096
#define SEQ   4096
#define BT    (BATCH * SEQ)

static __device__ __forceinline__ float ex2f_(float x) {
    float y; asm("ex2.approx.f32 %0, %1;" : "=f"(y) : "f"(x)); return y;
}
static __device__ __forceinline__ float rcpf_(float x) {
    float y; asm("rcp.approx.f32 %0, %1;" : "=f"(y) : "f"(x)); return y;
}
static __device__ __forceinline__ float tanhf_(float x) {
    float y; asm("tanh.approx.f32 %0, %1;" : "=f"(y) : "f"(x)); return y;
}

// ---------------------------------------------------------------------------
// Scan kernel: one thread = one chain; 1 warp/SM; latency-bound.
// Empirical law (R1/R2/R3/R4/R9): wall ~= 9-11 cyc per serial instruction,
// regardless of ILP. So: minimize instructions per step.
//   - two 4-step bodies per iteration, alternating buffers -> NO copy movs
//   - u = fmaf(-omz, h, h) kills the 0.5*h temporary
// Step (13 FMA/MUFU):
//   pxr,pxz,pxn (x-proj) ; sr,sz,hhn,c2 (h-proj) ; tr,tz ; omz,u ; sn ; tn ; h'
// ---------------------------------------------------------------------------
__global__ void __launch_bounds__(32, 1) gru_scan_kernel(
    const float* __restrict__ xi,    // (B, T, 2): [x, label]
    const float* __restrict__ Wih,   // (3,2) rows r,z,n
    const float* __restrict__ Whh,   // (3,)
    const float* __restrict__ bih,   // (3,)
    const float* __restrict__ bhh,   // (3,)
    float* __restrict__ hraw)        // (B, T) raw h
{
    const int b = blockIdx.x * 32 + threadIdx.x;

    const size_t rowoff = (size_t)b * (SEQ * 2);
    const float4* __restrict__ xrow = (const float4*)(xi + rowoff);
    const float label = xi[rowoff + 1];

    const float Ar = Wih[0], Br = Wih[1];
    const float Az = Wih[2], Bz = Wih[3];
    const float An = Wih[4], Bn = Wih[5];
    const float Wr = Whh[0], Wz = Whh[1], Wn = Whh[2];

    const float ar2 = 0.5f * Ar, wr2 = 0.5f * Wr;
    const float cr2 = 0.5f * (Br * label + bih[0] + bhh[0]);
    const float az2 = 0.5f * Az, wz2 = 0.5f * Wz;
    const float cz2 = 0.5f * (Bz * label + bih[1] + bhh[1]);
    const float wn2 = 0.5f * Wn, bn2 = 0.5f * bhh[2];
    const float anx = An;
    const float cnx = Bn * label + bih[2] + bn2;

    float h = 0.0f;
    float4* __restrict__ orow = (float4*)(hraw + (size_t)b * SEQ);

    // Two live buffers; bodies alternate, so no register copies ever.
    float4 a0 = xrow[0], a1 = xrow[1];
    float4 b0, b1;

    const int NPAIR = SEQ / 8;  // 512 iterations, 2 chunks of 4 steps each
    for (int p = 0; p < NPAIR; ++p) {
        // ---- prefetch chunk 2p+1 into b, then body A on a ----
        b0 = xrow[(2 * p + 1) * 2 + 0];
        b1 = xrow[(2 * p + 1) * 2 + 1];
        {
            float xs0 = a0.x, xs1 = a0.z, xs2 = a1.x, xs3 = a1.z;
            float xs[4] = {xs0, xs1, xs2, xs3};
            float y[4];
            #pragma unroll
            for (int s = 0; s < 4; ++s) {
                const float x   = xs[s];
                const float pxr = fmaf(ar2, x, cr2);
                const float pxz = fmaf(az2, x, cz2);
                const float pxn = fmaf(anx, x, cnx);
                const float sr  = fmaf(wr2, h, pxr);
                const float sz  = fmaf(wz2, h, pxz);
                const float hhn = fmaf(wn2, h, bn2);
                const float c2  = fmaf(wn2, h, pxn);
                const float tr  = tanhf_(sr);
                const float tz  = tanhf_(sz);
                const float omz = fmaf(-0.5f, tz, 0.5f);
                const float u   = fmaf(-omz, h, h);
                const float sn  = fmaf(tr, hhn, c2);
                const float tn  = tanhf_(sn);
                h = fmaf(omz, tn, u);
                y[s] = h;
            }
            orow[2 * p] = make_float4(y[0], y[1], y[2], y[3]);
        }

        // ---- prefetch chunk 2p+2 into a, then body B on b ----
        const int nx = (p + 1 < NPAIR) ? (2 * p + 2) : (2 * p + 1);
        a0 = xrow[nx * 2 + 0];
        a1 = xrow[nx * 2 + 1];
        {
            float xs0 = b0.x, xs1 = b0.z, xs2 = b1.x, xs3 = b1.z;
            float xs[4] = {xs0, xs1, xs2, xs3};
            float y[4];
            #pragma unroll
            for (int s = 0; s < 4; ++s) {
                const float x   = xs[s];
                const float pxr = fmaf(ar2, x, cr2);
                const float pxz = fmaf(az2, x, cz2);
                const float pxn = fmaf(anx, x, cnx);
                const float sr  = fmaf(wr2, h, pxr);
                const float sz  = fmaf(wz2, h, pxz);
                const float hhn = fmaf(wn2, h, bn2);
                const float c2  = fmaf(wn2, h, pxn);
                const float tr  = tanhf_(sr);
                const float tz  = tanhf_(sz);
                const float omz = fmaf(-0.5f, tz, 0.5f);
                const float u   = fmaf(-omz, h, h);
                const float sn  = fmaf(tr, hhn, c2);
                const float tn  = tanhf_(sn);
                h = fmaf(omz, tn, u);
                y[s] = h;
            }
            orow[2 * p + 1] = make_float4(y[0], y[1], y[2], y[3]);
        }
    }
}

// ---------------------------------------------------------------------------
// Finish kernel: in-place accurate tanh on raw h + labels broadcast fill.
// DRAM-bound (~4.7 TB/s); output tanh stays accurate (its error is undamped).
// ---------------------------------------------------------------------------
__global__ void finish_kernel(float4* __restrict__ out,        // BT/4 elems
                              const float* __restrict__ labels,
                              float4* __restrict__ outl)       // or nullptr
{
    const float S = -2.0f * 1.44269504088896340736f;
    int i = blockIdx.x * blockDim.x + threadIdx.x;
    float4 v = out[i];
    v.x = fmaf(2.0f, rcpf_(1.0f + ex2f_(S * v.x)), -1.0f);
    v.y = fmaf(2.0f, rcpf_(1.0f + ex2f_(S * v.y)), -1.0f);
    v.z = fmaf(2.0f, rcpf_(1.0f + ex2f_(S * v.z)), -1.0f);
    v.w = fmaf(2.0f, rcpf_(1.0f + ex2f_(S * v.w)), -1.0f);
    out[i] = v;
    if (outl) {
        const int bb = i >> 10;                     // SEQ/4 float4 per row
        const float lab = __ldg(labels + (size_t)bb * SEQ);
        outl[i] = make_float4(lab, lab, lab, lab);
    }
}

extern "C" void kernel_launch(void* const* d_in, const int* in_sizes, int n_in,
                              void* d_out, int out_size)
{
    const float* xi     = (const float*)d_in[0];
    const float* labels = (const float*)d_in[1];
    const float* Wih    = (const float*)d_in[2];
    const float* Whh    = (const float*)d_in[3];
    const float* bih    = (const float*)d_in[4];
    const float* bhh    = (const float*)d_in[5];

    float* out  = (float*)d_out;
    float* outl = (out_size >= 2 * BT) ? (out + (size_t)BT) : (float*)0;

    gru_scan_kernel<<<BATCH / 32, 32>>>(xi, Wih, Whh, bih, bhh, out);

    const int N4 = BT / 4;
    finish_kernel<<<N4 / 256, 256>>>((float4*)out, labels, (float4*)outl);
}